// round 14
// baseline (speedup 1.0000x reference)
#include <cuda_runtime.h>
#include <cuda_fp16.h>
#include <cstdint>
#include <math.h>

#define T_TOK 4096
#define EMB   1024
#define HID   2816
#define NE    8
#define NPAIR (T_TOK * 2)

// ---------------- device scratch ---------------------------------------------
__device__ int    g_offsets[NE + 1];
__device__ int    g_tok_e[T_TOK][2];
__device__ float  g_tok_p[T_TOK][2];
__device__ int    g_pair_token[NPAIR];
__device__ float  g_pair_gate[NPAIR];
__device__ int    g_pair_slot[NPAIR];
__device__ __align__(16) __half g_rx [(size_t)T_TOK * EMB];     // fp16 x
__device__ __align__(16) __half g_w1t[(size_t)NE * HID * EMB];  // w1^T [e][n][k]
__device__ __align__(16) __half g_w3t[(size_t)NE * HID * EMB];  // w3^T
__device__ __align__(16) __half g_w2t[(size_t)NE * EMB * HID];  // w2^T [e][n][k]
__device__ __align__(16) __half g_hbuf[(size_t)NPAIR * HID];    // silu(h)*g fp16
__device__ float  g_contrib[2][T_TOK][EMB];

// ---------------- helpers ----------------------------------------------------
__device__ __forceinline__ void mma_f16(float c[4], const uint32_t a[4], uint32_t b0, uint32_t b1) {
    asm volatile(
        "mma.sync.aligned.m16n8k16.row.col.f32.f16.f16.f32 "
        "{%0,%1,%2,%3}, {%4,%5,%6,%7}, {%8,%9}, {%0,%1,%2,%3};\n"
        : "+f"(c[0]), "+f"(c[1]), "+f"(c[2]), "+f"(c[3])
        : "r"(a[0]), "r"(a[1]), "r"(a[2]), "r"(a[3]), "r"(b0), "r"(b1));
}

__device__ __forceinline__ void ldsm4(uint32_t& r0, uint32_t& r1, uint32_t& r2, uint32_t& r3,
                                      uint32_t addr) {
    asm volatile("ldmatrix.sync.aligned.m8n8.x4.shared.b16 {%0,%1,%2,%3}, [%4];"
                 : "=r"(r0), "=r"(r1), "=r"(r2), "=r"(r3) : "r"(addr));
}

__device__ __forceinline__ void cpa(void* sdst, const void* gsrc, uint32_t pbytes) {
    uint32_t s = (uint32_t)__cvta_generic_to_shared(sdst);
    asm volatile("cp.async.cg.shared.global [%0], [%1], 16, %2;\n"
                 :: "r"(s), "l"(gsrc), "r"(pbytes));
}
#define CP_COMMIT asm volatile("cp.async.commit_group;\n" ::: "memory")
#define CP_WAIT1  asm volatile("cp.async.wait_group 1;\n" ::: "memory")
#define CP_WAIT0  asm volatile("cp.async.wait_group 0;\n" ::: "memory")

// ---------------- kernel 0: router + x->fp16 ---------------------------------
__global__ void router_kernel(const float* __restrict__ x, const float* __restrict__ wr) {
    int gw   = (blockIdx.x * blockDim.x + threadIdx.x) >> 5;
    int lane = threadIdx.x & 31;
    if (gw >= T_TOK) return;
    const float* xr = x + (size_t)gw * EMB;
    __half*      ox = g_rx + (size_t)gw * EMB;
    float acc[NE];
#pragma unroll
    for (int e = 0; e < NE; e++) acc[e] = 0.f;
    for (int k = lane; k < EMB; k += 32) {
        float xv = xr[k];
        ox[k] = __float2half_rn(xv);
        float4 wa = *(const float4*)(wr + k * NE);
        float4 wb = *(const float4*)(wr + k * NE + 4);
        acc[0] += xv * wa.x; acc[1] += xv * wa.y; acc[2] += xv * wa.z; acc[3] += xv * wa.w;
        acc[4] += xv * wb.x; acc[5] += xv * wb.y; acc[6] += xv * wb.z; acc[7] += xv * wb.w;
    }
#pragma unroll
    for (int e = 0; e < NE; e++)
#pragma unroll
        for (int o = 16; o > 0; o >>= 1) acc[e] += __shfl_xor_sync(0xffffffffu, acc[e], o);
    if (lane == 0) {
        int i0 = 0; float v0 = acc[0];
#pragma unroll
        for (int e = 1; e < NE; e++) if (acc[e] > v0) { v0 = acc[e]; i0 = e; }
        int i1 = -1; float v1 = -1e30f;
#pragma unroll
        for (int e = 0; e < NE; e++) if (e != i0 && acc[e] > v1) { v1 = acc[e]; i1 = e; }
        float p1 = 1.f / (1.f + expf(v0 - v1));
        g_tok_e[gw][0] = i0; g_tok_e[gw][1] = i1;
        g_tok_p[gw][0] = 1.f - p1; g_tok_p[gw][1] = p1;
    }
}

// ---------------- kernel 1: offsets + scatter (single CTA) --------------------
__global__ void offsets_scatter_kernel() {
    __shared__ int hist[8][NE];
    __shared__ int soff[NE];
    __shared__ int scur[NE];
    int tid = threadIdx.x, wid = tid >> 5;
    if (tid < 64) ((int*)hist)[tid] = 0;
    __syncthreads();
    for (int i = tid; i < NPAIR; i += 256) {
        int t = i >> 1, k = i & 1;
        atomicAdd(&hist[wid][g_tok_e[t][k]], 1);
    }
    __syncthreads();
    if (tid == 0) {
        int s = 0;
        for (int e = 0; e < NE; e++) {
            int c = 0;
            for (int w = 0; w < 8; w++) c += hist[w][e];
            g_offsets[e] = s; soff[e] = s; s += c;
        }
        g_offsets[NE] = s;
    }
    if (tid < NE) scur[tid] = 0;
    __syncthreads();
    for (int i = tid; i < NPAIR; i += 256) {
        int t = i >> 1, k = i & 1;
        int e = g_tok_e[t][k];
        int pos = soff[e] + atomicAdd(&scur[e], 1);
        g_pair_token[pos] = t;
        g_pair_gate[pos]  = g_tok_p[t][k];
        g_pair_slot[pos]  = k;
    }
}

// ---------------- kernel 2: weights -> fp16, transposed to [e][n][k] ---------
__global__ void preround_w_kernel(const float* __restrict__ w1,
                                  const float* __restrict__ w3,
                                  const float* __restrict__ w2) {
    __shared__ float tile[32][33];
    int z = blockIdx.z;
    int r = threadIdx.x >> 5, c = threadIdx.x & 31;
    if (z < 16) {
        int e = z & 7;
        const float* src = (z >= 8 ? w3 : w1) + (size_t)e * EMB * HID;
        __half*      dst = (z >= 8 ? g_w3t : g_w1t) + (size_t)e * HID * EMB;
        int n0 = blockIdx.x * 32;   // HID
        int k0 = blockIdx.y * 32;   // EMB
#pragma unroll
        for (int i = 0; i < 4; i++)
            tile[r + i * 8][c] = src[(size_t)(k0 + r + i * 8) * HID + n0 + c];
        __syncthreads();
#pragma unroll
        for (int i = 0; i < 4; i++)
            dst[(size_t)(n0 + r + i * 8) * EMB + k0 + c] = __float2half_rn(tile[c][r + i * 8]);
    } else {
        int e = z - 16;
        const float* src = w2 + (size_t)e * HID * EMB;
        __half*      dst = g_w2t + (size_t)e * EMB * HID;
        int k0 = blockIdx.x * 32;   // HID
        int n0 = blockIdx.y * 32;   // EMB
#pragma unroll
        for (int i = 0; i < 4; i++)
            tile[r + i * 8][c] = src[(size_t)(k0 + r + i * 8) * EMB + n0 + c];
        __syncthreads();
#pragma unroll
        for (int i = 0; i < 4; i++)
            dst[(size_t)(n0 + r + i * 8) * HID + k0 + c] = __float2half_rn(tile[c][r + i * 8]);
    }
}

// ---------------- GEMM tiling constants --------------------------------------
#define BK   64                       /* halves per K-chunk */
#define ASTR 72                       /* half stride: 144B rows, 16B aligned, conflict-free */
#define A_BYTES (128 * ASTR * 2)      /* 18432 B */
#define B_BYTES (128 * ASTR * 2)      /* 18432 B (ffn1: 64 w1-rows + 64 w3-rows) */
#define F_STG   (A_BYTES + B_BYTES)   /* 36864 B */
#define F_SMEM  (3 * F_STG)           /* 110592 B -> 2 CTAs/SM */

// ---------------- kernel 3: ffn1 fp16 GEMM + SwiGLU --------------------------
// CTA: 128 pairs x 64 swiglu cols (64 w1-cols + 64 w3-cols in one B buffer).
// Warps 4(M) x 2(N-half); warp tile 32M x (32 w1 + 32 w3). BK=64, 3 stages.
__global__ void __launch_bounds__(256, 2) ffn1_kernel() {
    extern __shared__ __align__(16) char smem[];

    int e = blockIdx.z, nt = blockIdx.y, mt = blockIdx.x;
    int pbeg = g_offsets[e], pend = g_offsets[e + 1];
    int m0 = pbeg + mt * 128;
    if (m0 >= pend) return;
    int mcnt = pend - m0; if (mcnt > 128) mcnt = 128;

    int tid = threadIdx.x;
    int warp = tid >> 5, lane = tid & 31;
    int wm = warp & 3, wn = warp >> 2;
    int gid = lane >> 2, tig = lane & 3;

    int  arow = tid >> 1, aseg = tid & 1;
    bool av   = arow < mcnt;
    int  atok = av ? g_pair_token[m0 + arow] : 0;
    const __half* asrc = g_rx + (size_t)atok * EMB;
    uint32_t apb = av ? 16u : 0u;

    int brow = tid >> 1, bseg = tid & 1;   // 128 B-rows: 0-63 w1, 64-127 w3
    const __half* bsrc = (brow < 64)
        ? g_w1t + ((size_t)e * HID + (size_t)nt * 64 + brow) * EMB
        : g_w3t + ((size_t)e * HID + (size_t)nt * 64 + (brow - 64)) * EMB;

    float ch[2][4][4], cg[2][4][4];
#pragma unroll
    for (int a = 0; a < 2; a++)
#pragma unroll
        for (int b = 0; b < 4; b++)
#pragma unroll
            for (int c = 0; c < 4; c++) { ch[a][b][c] = 0.f; cg[a][b][c] = 0.f; }

    uint32_t sbase = (uint32_t)__cvta_generic_to_shared(smem);
    int l16 = lane & 15, lkq = (lane >> 4) * 8;
    uint32_t aoff0 = ((wm * 32 + l16) * ASTR + lkq) * 2;
    uint32_t aoff1 = aoff0 + 16 * ASTR * 2;
    int l8 = lane & 7, q = lane >> 3;
    uint32_t b1off0 = ((wn * 32 + (q >> 1) * 8 + l8) * ASTR + (q & 1) * 8) * 2;
    uint32_t b1off1 = b1off0 + 16 * ASTR * 2;
    uint32_t b3off0 = b1off0 + 64 * ASTR * 2;
    uint32_t b3off1 = b1off1 + 64 * ASTR * 2;

    auto LOAD = [&](int s, int k0) {
        char* A = smem + s * F_STG;
        char* B = A + A_BYTES;
#pragma unroll
        for (int j = 0; j < 4; j++) {
            int c16 = aseg * 4 + j;          // 16B chunk 0..7 of a 128B row
            cpa(A + (arow * ASTR + c16 * 8) * 2, asrc + k0 + c16 * 8, apb);
        }
#pragma unroll
        for (int j = 0; j < 4; j++) {
            int c16 = bseg * 4 + j;
            cpa(B + (brow * ASTR + c16 * 8) * 2, bsrc + k0 + c16 * 8, 16);
        }
        CP_COMMIT;
    };

    LOAD(0, 0);
    LOAD(1, BK);

    const int NIT = EMB / BK;   // 16
    for (int it = 0; it < NIT; ++it) {
        int cur = it - (it / 3) * 3;
        if (it == NIT - 1) { CP_WAIT0; } else { CP_WAIT1; }
        __syncthreads();
        if (it + 2 < NIT) {
            int nxt = cur + 2; if (nxt >= 3) nxt -= 3;
            LOAD(nxt, (it + 2) * BK);
        }

        uint32_t sA = sbase + cur * F_STG;
        uint32_t sB = sA + A_BYTES;
#pragma unroll
        for (int kk = 0; kk < BK; kk += 16) {
            uint32_t a[2][4], b1r[8], b3r[8];
            ldsm4(a[0][0], a[0][1], a[0][2], a[0][3], sA + aoff0 + kk * 2);
            ldsm4(a[1][0], a[1][1], a[1][2], a[1][3], sA + aoff1 + kk * 2);
            ldsm4(b1r[0], b1r[1], b1r[2], b1r[3], sB + b1off0 + kk * 2);
            ldsm4(b1r[4], b1r[5], b1r[6], b1r[7], sB + b1off1 + kk * 2);
            ldsm4(b3r[0], b3r[1], b3r[2], b3r[3], sB + b3off0 + kk * 2);
            ldsm4(b3r[4], b3r[5], b3r[6], b3r[7], sB + b3off1 + kk * 2);
#pragma unroll
            for (int ni = 0; ni < 4; ni++) {
                int bi = (ni >> 1) * 4 + (ni & 1) * 2;
#pragma unroll
                for (int mi = 0; mi < 2; mi++) {
                    mma_f16(ch[mi][ni], a[mi], b1r[bi], b1r[bi + 1]);
                    mma_f16(cg[mi][ni], a[mi], b3r[bi], b3r[bi + 1]);
                }
            }
        }
    }

    // epilogue: silu(h)*g -> fp16 hbuf (half2 stores)
#pragma unroll
    for (int mi = 0; mi < 2; mi++) {
        int r0 = wm * 32 + mi * 16 + gid;
#pragma unroll
        for (int ni = 0; ni < 4; ni++) {
            int colg = nt * 64 + wn * 32 + ni * 8 + tig * 2;
            if (r0 < mcnt) {
                float h0 = ch[mi][ni][0], g0 = cg[mi][ni][0];
                float h1 = ch[mi][ni][1], g1 = cg[mi][ni][1];
                __half2 v = __floats2half2_rn((h0 / (1.f + expf(-h0))) * g0,
                                              (h1 / (1.f + expf(-h1))) * g1);
                *(__half2*)&g_hbuf[(size_t)(m0 + r0) * HID + colg] = v;
            }
            if (r0 + 8 < mcnt) {
                float h0 = ch[mi][ni][2], g0 = cg[mi][ni][2];
                float h1 = ch[mi][ni][3], g1 = cg[mi][ni][3];
                __half2 v = __floats2half2_rn((h0 / (1.f + expf(-h0))) * g0,
                                              (h1 / (1.f + expf(-h1))) * g1);
                *(__half2*)&g_hbuf[(size_t)(m0 + r0 + 8) * HID + colg] = v;
            }
        }
    }
}

// ---------------- kernel 4: ffn2 fp16 GEMM (h @ w2) * gate -------------------
// CTA: 128 pairs x 128 emb cols. Warps 4(M) x 2(N); warp tile 32x64. BK=64.
__global__ void __launch_bounds__(256, 2) ffn2_kernel() {
    extern __shared__ __align__(16) char smem[];

    int e = blockIdx.z, nt = blockIdx.y, mt = blockIdx.x;
    int pbeg = g_offsets[e], pend = g_offsets[e + 1];
    int m0 = pbeg + mt * 128;
    if (m0 >= pend) return;
    int mcnt = pend - m0; if (mcnt > 128) mcnt = 128;

    int tid = threadIdx.x;
    int warp = tid >> 5, lane = tid & 31;
    int wm = warp & 3, wn = warp >> 2;
    int gid = lane >> 2, tig = lane & 3;

    int  arow = tid >> 1, aseg = tid & 1;
    bool av   = arow < mcnt;
    const __half* asrc = g_hbuf + (size_t)(m0 + (av ? arow : 0)) * HID;
    uint32_t apb = av ? 16u : 0u;

    int brow = tid >> 1, bseg = tid & 1;
    const __half* bsrc = g_w2t + ((size_t)e * EMB + (size_t)nt * 128 + brow) * HID;

    float acc[2][8][4];
#pragma unroll
    for (int a = 0; a < 2; a++)
#pragma unroll
        for (int b = 0; b < 8; b++)
#pragma unroll
            for (int c = 0; c < 4; c++) acc[a][b][c] = 0.f;

    uint32_t sbase = (uint32_t)__cvta_generic_to_shared(smem);
    int l16 = lane & 15, lkq = (lane >> 4) * 8;
    uint32_t aoff0 = ((wm * 32 + l16) * ASTR + lkq) * 2;
    uint32_t aoff1 = aoff0 + 16 * ASTR * 2;
    int l8 = lane & 7, q = lane >> 3;
    uint32_t boff[4];
#pragma unroll
    for (int g = 0; g < 4; g++)
        boff[g] = ((wn * 64 + g * 16 + (q >> 1) * 8 + l8) * ASTR + (q & 1) * 8) * 2;

    auto LOAD = [&](int s, int k0) {
        char* A = smem + s * F_STG;
        char* B = A + A_BYTES;
#pragma unroll
        for (int j = 0; j < 4; j++) {
            int c16 = aseg * 4 + j;
            cpa(A + (arow * ASTR + c16 * 8) * 2, asrc + k0 + c16 * 8, apb);
        }
#pragma unroll
        for (int j = 0; j < 4; j++) {
            int c16 = bseg * 4 + j;
            cpa(B + (brow * ASTR + c16 * 8) * 2, bsrc + k0 + c16 * 8, 16);
        }
        CP_COMMIT;
    };

    LOAD(0, 0);
    LOAD(1, BK);

    const int NIT = HID / BK;   // 44
    for (int it = 0; it < NIT; ++it) {
        int cur = it - (it / 3) * 3;
        if (it == NIT - 1) { CP_WAIT0; } else { CP_WAIT1; }
        __syncthreads();
        if (it + 2 < NIT) {
            int nxt = cur + 2; if (nxt >= 3) nxt -= 3;
            LOAD(nxt, (it + 2) * BK);
        }

        uint32_t sA = sbase + cur * F_STG;
        uint32_t sB = sA + A_BYTES;
#pragma unroll
        for (int kk = 0; kk < BK; kk += 16) {
            uint32_t a[2][4], br[16];
            ldsm4(a[0][0], a[0][1], a[0][2], a[0][3], sA + aoff0 + kk * 2);
            ldsm4(a[1][0], a[1][1], a[1][2], a[1][3], sA + aoff1 + kk * 2);
#pragma unroll
            for (int g = 0; g < 4; g++)
                ldsm4(br[g * 4], br[g * 4 + 1], br[g * 4 + 2], br[g * 4 + 3],
                      sB + boff[g] + kk * 2);
#pragma unroll
            for (int ni = 0; ni < 8; ni++) {
                int bi = (ni >> 1) * 4 + (ni & 1) * 2;
#pragma unroll
                for (int mi = 0; mi < 2; mi++)
                    mma_f16(acc[mi][ni], a[mi], br[bi], br[bi + 1]);
            }
        }
    }

    // epilogue: gate * acc -> per-slot contribution buffer (float2 stores)
#pragma unroll
    for (int mi = 0; mi < 2; mi++) {
        int r0 = wm * 32 + mi * 16 + gid;
        int   t0 = 0, t1 = 0, s0 = 0, s1 = 0;
        float gt0 = 0.f, gt1 = 0.f;
        bool v0 = r0 < mcnt, v1 = (r0 + 8) < mcnt;
        if (v0) { int p = m0 + r0;     t0 = g_pair_token[p]; gt0 = g_pair_gate[p]; s0 = g_pair_slot[p]; }
        if (v1) { int p = m0 + r0 + 8; t1 = g_pair_token[p]; gt1 = g_pair_gate[p]; s1 = g_pair_slot[p]; }
#pragma unroll
        for (int ni = 0; ni < 8; ni++) {
            int colg = nt * 128 + wn * 64 + ni * 8 + tig * 2;
            if (v0) {
                float2 v = make_float2(acc[mi][ni][0] * gt0, acc[mi][ni][1] * gt0);
                *(float2*)&g_contrib[s0][t0][colg] = v;
            }
            if (v1) {
                float2 v = make_float2(acc[mi][ni][2] * gt1, acc[mi][ni][3] * gt1);
                *(float2*)&g_contrib[s1][t1][colg] = v;
            }
        }
    }
}

// ---------------- kernel 5: final reduce -------------------------------------
__global__ void reduce_kernel(float* __restrict__ out) {
    size_t i = (size_t)blockIdx.x * blockDim.x + threadIdx.x;
    size_t n = (size_t)T_TOK * EMB / 4;
    if (i >= n) return;
    const float4* c0 = (const float4*)&g_contrib[0][0][0];
    const float4* c1 = (const float4*)&g_contrib[1][0][0];
    float4 a = c0[i], b = c1[i];
    ((float4*)out)[i] = make_float4(a.x + b.x, a.y + b.y, a.z + b.z, a.w + b.w);
}

// ---------------- launch ------------------------------------------------------
extern "C" void kernel_launch(void* const* d_in, const int* in_sizes, int n_in,
                              void* d_out, int out_size) {
    const float* x  = (const float*)d_in[0];
    const float* wr = (const float*)d_in[1];
    const float* w1 = (const float*)d_in[2];
    const float* w3 = (const float*)d_in[3];
    const float* w2 = (const float*)d_in[4];
    float* out = (float*)d_out;

    cudaFuncSetAttribute(ffn1_kernel, cudaFuncAttributeMaxDynamicSharedMemorySize, F_SMEM);
    cudaFuncSetAttribute(ffn2_kernel, cudaFuncAttributeMaxDynamicSharedMemorySize, F_SMEM);

    router_kernel<<<(T_TOK * 32 + 255) / 256, 256>>>(x, wr);           // 0
    offsets_scatter_kernel<<<1, 256>>>();                              // 1
    preround_w_kernel<<<dim3(88, 32, 24), 256>>>(w1, w3, w2);          // 2

    ffn1_kernel<<<dim3(32, HID / 64, NE), 256, F_SMEM>>>();            // 3  <- ncu capture
    ffn2_kernel<<<dim3(32, EMB / 128, NE), 256, F_SMEM>>>();           // 4
    reduce_kernel<<<((T_TOK * EMB / 4) + 255) / 256, 256>>>(out);      // 5
}

// round 15
// speedup vs baseline: 1.0819x; 1.0819x over previous
#include <cuda_runtime.h>
#include <cuda_fp16.h>
#include <cstdint>
#include <math.h>

#define T_TOK 4096
#define EMB   1024
#define HID   2816
#define NE    8
#define NPAIR (T_TOK * 2)

// ---------------- device scratch ---------------------------------------------
__device__ int    g_offsets[NE + 1];
__device__ int    g_tok_e[T_TOK][2];
__device__ float  g_tok_p[T_TOK][2];
__device__ int    g_pair_token[NPAIR];
__device__ float  g_pair_gate[NPAIR];
__device__ int    g_pair_slot[NPAIR];
__device__ __align__(16) __half g_rx [(size_t)T_TOK * EMB];     // fp16 x
__device__ __align__(16) __half g_w1t[(size_t)NE * HID * EMB];  // w1^T [e][n][k]
__device__ __align__(16) __half g_w3t[(size_t)NE * HID * EMB];  // w3^T
__device__ __align__(16) __half g_w2t[(size_t)NE * EMB * HID];  // w2^T [e][n][k]
__device__ __align__(16) __half g_hbuf[(size_t)NPAIR * HID];    // silu(h)*g fp16
__device__ float  g_contrib[2][T_TOK][EMB];

// ---------------- helpers ----------------------------------------------------
__device__ __forceinline__ void mma_f16(float c[4], const uint32_t a[4], uint32_t b0, uint32_t b1) {
    asm volatile(
        "mma.sync.aligned.m16n8k16.row.col.f32.f16.f16.f32 "
        "{%0,%1,%2,%3}, {%4,%5,%6,%7}, {%8,%9}, {%0,%1,%2,%3};\n"
        : "+f"(c[0]), "+f"(c[1]), "+f"(c[2]), "+f"(c[3])
        : "r"(a[0]), "r"(a[1]), "r"(a[2]), "r"(a[3]), "r"(b0), "r"(b1));
}

__device__ __forceinline__ void ldsm4(uint32_t& r0, uint32_t& r1, uint32_t& r2, uint32_t& r3,
                                      uint32_t addr) {
    asm volatile("ldmatrix.sync.aligned.m8n8.x4.shared.b16 {%0,%1,%2,%3}, [%4];"
                 : "=r"(r0), "=r"(r1), "=r"(r2), "=r"(r3) : "r"(addr));
}

__device__ __forceinline__ void cpa(void* sdst, const void* gsrc, uint32_t pbytes) {
    uint32_t s = (uint32_t)__cvta_generic_to_shared(sdst);
    asm volatile("cp.async.cg.shared.global [%0], [%1], 16, %2;\n"
                 :: "r"(s), "l"(gsrc), "r"(pbytes));
}
#define CP_COMMIT asm volatile("cp.async.commit_group;\n" ::: "memory")
#define CP_WAIT1  asm volatile("cp.async.wait_group 1;\n" ::: "memory")
#define CP_WAIT0  asm volatile("cp.async.wait_group 0;\n" ::: "memory")

// ---------------- kernel 0: preround weights + router (merged) ---------------
// grid (88, 32, 25), 256 threads. z<16: w1/w3 transpose; z<24: w2; z==24: router.
__global__ void prep_kernel(const float* __restrict__ w1,
                            const float* __restrict__ w3,
                            const float* __restrict__ w2,
                            const float* __restrict__ x,
                            const float* __restrict__ wr) {
    int z = blockIdx.z;
    if (z == 24) {
        int bid = blockIdx.y * 88 + blockIdx.x;
        if (bid >= 512) return;
        int gw   = bid * 8 + (threadIdx.x >> 5);   // token
        int lane = threadIdx.x & 31;
        const float* xr = x + (size_t)gw * EMB;
        __half*      ox = g_rx + (size_t)gw * EMB;
        float acc[NE];
#pragma unroll
        for (int e = 0; e < NE; e++) acc[e] = 0.f;
        for (int k = lane; k < EMB; k += 32) {
            float xv = xr[k];
            ox[k] = __float2half_rn(xv);
            float4 wa = *(const float4*)(wr + k * NE);
            float4 wb = *(const float4*)(wr + k * NE + 4);
            acc[0] += xv * wa.x; acc[1] += xv * wa.y; acc[2] += xv * wa.z; acc[3] += xv * wa.w;
            acc[4] += xv * wb.x; acc[5] += xv * wb.y; acc[6] += xv * wb.z; acc[7] += xv * wb.w;
        }
#pragma unroll
        for (int e = 0; e < NE; e++)
#pragma unroll
            for (int o = 16; o > 0; o >>= 1) acc[e] += __shfl_xor_sync(0xffffffffu, acc[e], o);
        if (lane == 0) {
            int i0 = 0; float v0 = acc[0];
#pragma unroll
            for (int e = 1; e < NE; e++) if (acc[e] > v0) { v0 = acc[e]; i0 = e; }
            int i1 = -1; float v1 = -1e30f;
#pragma unroll
            for (int e = 0; e < NE; e++) if (e != i0 && acc[e] > v1) { v1 = acc[e]; i1 = e; }
            float p1 = 1.f / (1.f + expf(v0 - v1));
            g_tok_e[gw][0] = i0; g_tok_e[gw][1] = i1;
            g_tok_p[gw][0] = 1.f - p1; g_tok_p[gw][1] = p1;
        }
        return;
    }
    __shared__ float tile[32][33];
    int r = threadIdx.x >> 5, c = threadIdx.x & 31;
    if (z < 16) {
        int e = z & 7;
        const float* src = (z >= 8 ? w3 : w1) + (size_t)e * EMB * HID;
        __half*      dst = (z >= 8 ? g_w3t : g_w1t) + (size_t)e * HID * EMB;
        int n0 = blockIdx.x * 32;   // HID
        int k0 = blockIdx.y * 32;   // EMB
#pragma unroll
        for (int i = 0; i < 4; i++)
            tile[r + i * 8][c] = src[(size_t)(k0 + r + i * 8) * HID + n0 + c];
        __syncthreads();
#pragma unroll
        for (int i = 0; i < 4; i++)
            dst[(size_t)(n0 + r + i * 8) * EMB + k0 + c] = __float2half_rn(tile[c][r + i * 8]);
    } else {
        int e = z - 16;
        const float* src = w2 + (size_t)e * HID * EMB;
        __half*      dst = g_w2t + (size_t)e * EMB * HID;
        int k0 = blockIdx.x * 32;   // HID
        int n0 = blockIdx.y * 32;   // EMB
#pragma unroll
        for (int i = 0; i < 4; i++)
            tile[r + i * 8][c] = src[(size_t)(k0 + r + i * 8) * EMB + n0 + c];
        __syncthreads();
#pragma unroll
        for (int i = 0; i < 4; i++)
            dst[(size_t)(n0 + r + i * 8) * HID + k0 + c] = __float2half_rn(tile[c][r + i * 8]);
    }
}

// ---------------- kernel 1: offsets + scatter (single CTA) --------------------
__global__ void offsets_scatter_kernel() {
    __shared__ int hist[8][NE];
    __shared__ int soff[NE];
    __shared__ int scur[NE];
    int tid = threadIdx.x, wid = tid >> 5;
    if (tid < 64) ((int*)hist)[tid] = 0;
    __syncthreads();
    for (int i = tid; i < NPAIR; i += 256) {
        int t = i >> 1, k = i & 1;
        atomicAdd(&hist[wid][g_tok_e[t][k]], 1);
    }
    __syncthreads();
    if (tid == 0) {
        int s = 0;
        for (int e = 0; e < NE; e++) {
            int c = 0;
            for (int w = 0; w < 8; w++) c += hist[w][e];
            g_offsets[e] = s; soff[e] = s; s += c;
        }
        g_offsets[NE] = s;
    }
    if (tid < NE) scur[tid] = 0;
    __syncthreads();
    for (int i = tid; i < NPAIR; i += 256) {
        int t = i >> 1, k = i & 1;
        int e = g_tok_e[t][k];
        int pos = soff[e] + atomicAdd(&scur[e], 1);
        g_pair_token[pos] = t;
        g_pair_gate[pos]  = g_tok_p[t][k];
        g_pair_slot[pos]  = k;
    }
}

// ---------------- GEMM tiling constants --------------------------------------
#define BK   32
#define ASTR 40                      /* halves: 80B rows, ldmatrix conflict-free */
#define F1_AS  (128 * ASTR * 2)      /* 10240 B */
#define F1_BS  (64 * ASTR * 2)       /* 5120 B  */
#define F1_STG (F1_AS + 2 * F1_BS)   /* 20480 B */
#define F1_SMEM (3 * F1_STG)         /* 61440 B */
#define F2_AS  (128 * ASTR * 2)
#define F2_BS  (128 * ASTR * 2)
#define F2_STG (F2_AS + F2_BS)       /* 20480 B */
#define F2_SMEM (3 * F2_STG)         /* 61440 B */

// ---------------- kernel 2: ffn1 fp16 GEMM + SwiGLU --------------------------
// CTA: 128 pairs x 64 hid cols, both w1 & w3. 3-stage cp.async.
// All 12 ldsm for both k16 slices hoisted to iteration start.
__global__ void __launch_bounds__(256, 2) ffn1_kernel() {
    extern __shared__ __align__(16) char smem[];

    int e = blockIdx.z, nt = blockIdx.y, mt = blockIdx.x;
    int pbeg = g_offsets[e], pend = g_offsets[e + 1];
    int m0 = pbeg + mt * 128;
    if (m0 >= pend) return;
    int mcnt = pend - m0; if (mcnt > 128) mcnt = 128;

    int tid = threadIdx.x;
    int warp = tid >> 5, lane = tid & 31;
    int wm = warp & 3, wn = warp >> 2;
    int gid = lane >> 2, tig = lane & 3;

    int  arow = tid >> 1, aseg = tid & 1;
    bool av   = arow < mcnt;
    int  atok = av ? g_pair_token[m0 + arow] : 0;
    const __half* asrc = g_rx + (size_t)atok * EMB + aseg * 16;
    uint32_t apb = av ? 16u : 0u;

    int brow = tid >> 2, bseg = tid & 3;
    const __half* b1b = g_w1t + ((size_t)e * HID + (size_t)nt * 64 + brow) * EMB + bseg * 8;
    const __half* b3b = g_w3t + ((size_t)e * HID + (size_t)nt * 64 + brow) * EMB + bseg * 8;

    float ch[2][4][4], cg[2][4][4];
#pragma unroll
    for (int a = 0; a < 2; a++)
#pragma unroll
        for (int b = 0; b < 4; b++)
#pragma unroll
            for (int c = 0; c < 4; c++) { ch[a][b][c] = 0.f; cg[a][b][c] = 0.f; }

    uint32_t sbase = (uint32_t)__cvta_generic_to_shared(smem);
    int l16 = lane & 15, lkq = (lane >> 4) * 8;
    uint32_t aoff0 = ((wm * 32 + l16) * ASTR + lkq) * 2;
    uint32_t aoff1 = aoff0 + 16 * ASTR * 2;
    int l8 = lane & 7, q = lane >> 3;
    uint32_t boff0 = ((wn * 32 + (q >> 1) * 8 + l8) * ASTR + (q & 1) * 8) * 2;
    uint32_t boff1 = boff0 + 16 * ASTR * 2;

    auto LOAD = [&](int s, int k0) {
        char* A  = smem + s * F1_STG;
        char* B1 = A + F1_AS;
        char* B3 = B1 + F1_BS;
        cpa(A + (arow * ASTR + aseg * 16) * 2,     asrc + k0,     apb);
        cpa(A + (arow * ASTR + aseg * 16 + 8) * 2, asrc + k0 + 8, apb);
        cpa(B1 + (brow * ASTR + bseg * 8) * 2, b1b + k0, 16);
        cpa(B3 + (brow * ASTR + bseg * 8) * 2, b3b + k0, 16);
        CP_COMMIT;
    };

    LOAD(0, 0);
    LOAD(1, BK);

    const int NIT = EMB / BK;
    for (int it = 0; it < NIT; ++it) {
        int cur = it - (it / 3) * 3;
        if (it == NIT - 1) { CP_WAIT0; } else { CP_WAIT1; }
        __syncthreads();
        if (it + 2 < NIT) {
            int nxt = cur + 2; if (nxt >= 3) nxt -= 3;
            LOAD(nxt, (it + 2) * BK);
        }

        uint32_t sA  = sbase + cur * F1_STG;
        uint32_t sB1 = sA + F1_AS;
        uint32_t sB3 = sB1 + F1_BS;

        // hoist ALL fragment loads for both k16 slices
        uint32_t a[2][2][4], b1r[2][8], b3r[2][8];
#pragma unroll
        for (int s2 = 0; s2 < 2; s2++) {
            int kb = s2 * 32;   // kk*2 bytes
            ldsm4(a[s2][0][0], a[s2][0][1], a[s2][0][2], a[s2][0][3], sA + aoff0 + kb);
            ldsm4(a[s2][1][0], a[s2][1][1], a[s2][1][2], a[s2][1][3], sA + aoff1 + kb);
            ldsm4(b1r[s2][0], b1r[s2][1], b1r[s2][2], b1r[s2][3], sB1 + boff0 + kb);
            ldsm4(b1r[s2][4], b1r[s2][5], b1r[s2][6], b1r[s2][7], sB1 + boff1 + kb);
            ldsm4(b3r[s2][0], b3r[s2][1], b3r[s2][2], b3r[s2][3], sB3 + boff0 + kb);
            ldsm4(b3r[s2][4], b3r[s2][5], b3r[s2][6], b3r[s2][7], sB3 + boff1 + kb);
        }
#pragma unroll
        for (int s2 = 0; s2 < 2; s2++)
#pragma unroll
            for (int ni = 0; ni < 4; ni++) {
                int bi = (ni >> 1) * 4 + (ni & 1) * 2;
#pragma unroll
                for (int mi = 0; mi < 2; mi++) {
                    mma_f16(ch[mi][ni], a[s2][mi], b1r[s2][bi], b1r[s2][bi + 1]);
                    mma_f16(cg[mi][ni], a[s2][mi], b3r[s2][bi], b3r[s2][bi + 1]);
                }
            }
    }

    // epilogue: silu(h)*g -> fp16 hbuf (half2 stores)
#pragma unroll
    for (int mi = 0; mi < 2; mi++) {
        int r0 = wm * 32 + mi * 16 + gid;
#pragma unroll
        for (int ni = 0; ni < 4; ni++) {
            int colg = nt * 64 + wn * 32 + ni * 8 + tig * 2;
            if (r0 < mcnt) {
                float h0 = ch[mi][ni][0], g0 = cg[mi][ni][0];
                float h1 = ch[mi][ni][1], g1 = cg[mi][ni][1];
                __half2 v = __floats2half2_rn((h0 / (1.f + expf(-h0))) * g0,
                                              (h1 / (1.f + expf(-h1))) * g1);
                *(__half2*)&g_hbuf[(size_t)(m0 + r0) * HID + colg] = v;
            }
            if (r0 + 8 < mcnt) {
                float h0 = ch[mi][ni][2], g0 = cg[mi][ni][2];
                float h1 = ch[mi][ni][3], g1 = cg[mi][ni][3];
                __half2 v = __floats2half2_rn((h0 / (1.f + expf(-h0))) * g0,
                                              (h1 / (1.f + expf(-h1))) * g1);
                *(__half2*)&g_hbuf[(size_t)(m0 + r0 + 8) * HID + colg] = v;
            }
        }
    }
}

// ---------------- kernel 3: ffn2 fp16 GEMM (h @ w2) * gate -------------------
__global__ void __launch_bounds__(256, 2) ffn2_kernel() {
    extern __shared__ __align__(16) char smem[];

    int e = blockIdx.z, nt = blockIdx.y, mt = blockIdx.x;
    int pbeg = g_offsets[e], pend = g_offsets[e + 1];
    int m0 = pbeg + mt * 128;
    if (m0 >= pend) return;
    int mcnt = pend - m0; if (mcnt > 128) mcnt = 128;

    int tid = threadIdx.x;
    int warp = tid >> 5, lane = tid & 31;
    int wm = warp & 3, wn = warp >> 2;
    int gid = lane >> 2, tig = lane & 3;

    int  arow = tid >> 1, aseg = tid & 1;
    bool av   = arow < mcnt;
    const __half* asrc = g_hbuf + (size_t)(m0 + (av ? arow : 0)) * HID + aseg * 16;
    uint32_t apb = av ? 16u : 0u;
    const __half* b2b = g_w2t + ((size_t)e * EMB + (size_t)nt * 128 + arow) * HID + aseg * 16;

    float acc[2][8][4];
#pragma unroll
    for (int a = 0; a < 2; a++)
#pragma unroll
        for (int b = 0; b < 8; b++)
#pragma unroll
            for (int c = 0; c < 4; c++) acc[a][b][c] = 0.f;

    uint32_t sbase = (uint32_t)__cvta_generic_to_shared(smem);
    int l16 = lane & 15, lkq = (lane >> 4) * 8;
    uint32_t aoff0 = ((wm * 32 + l16) * ASTR + lkq) * 2;
    uint32_t aoff1 = aoff0 + 16 * ASTR * 2;
    int l8 = lane & 7, q = lane >> 3;
    uint32_t boff[4];
#pragma unroll
    for (int g = 0; g < 4; g++)
        boff[g] = ((wn * 64 + g * 16 + (q >> 1) * 8 + l8) * ASTR + (q & 1) * 8) * 2;

    auto LOAD = [&](int s, int k0) {
        char* A = smem + s * F2_STG;
        char* B = A + F2_AS;
        cpa(A + (arow * ASTR + aseg * 16) * 2,     asrc + k0,     apb);
        cpa(A + (arow * ASTR + aseg * 16 + 8) * 2, asrc + k0 + 8, apb);
        cpa(B + (arow * ASTR + aseg * 16) * 2,     b2b + k0,     16);
        cpa(B + (arow * ASTR + aseg * 16 + 8) * 2, b2b + k0 + 8, 16);
        CP_COMMIT;
    };

    LOAD(0, 0);
    LOAD(1, BK);

    const int NIT = HID / BK;
    for (int it = 0; it < NIT; ++it) {
        int cur = it - (it / 3) * 3;
        if (it == NIT - 1) { CP_WAIT0; } else { CP_WAIT1; }
        __syncthreads();
        if (it + 2 < NIT) {
            int nxt = cur + 2; if (nxt >= 3) nxt -= 3;
            LOAD(nxt, (it + 2) * BK);
        }

        uint32_t sA = sbase + cur * F2_STG;
        uint32_t sB = sA + F2_AS;

        uint32_t a[2][2][4], br[2][16];
#pragma unroll
        for (int s2 = 0; s2 < 2; s2++) {
            int kb = s2 * 32;
            ldsm4(a[s2][0][0], a[s2][0][1], a[s2][0][2], a[s2][0][3], sA + aoff0 + kb);
            ldsm4(a[s2][1][0], a[s2][1][1], a[s2][1][2], a[s2][1][3], sA + aoff1 + kb);
#pragma unroll
            for (int g = 0; g < 4; g++)
                ldsm4(br[s2][g * 4], br[s2][g * 4 + 1], br[s2][g * 4 + 2], br[s2][g * 4 + 3],
                      sB + boff[g] + kb);
        }
#pragma unroll
        for (int s2 = 0; s2 < 2; s2++)
#pragma unroll
            for (int ni = 0; ni < 8; ni++) {
                int bi = (ni >> 1) * 4 + (ni & 1) * 2;
#pragma unroll
                for (int mi = 0; mi < 2; mi++)
                    mma_f16(acc[mi][ni], a[s2][mi], br[s2][bi], br[s2][bi + 1]);
            }
    }

    // epilogue: gate * acc -> per-slot contribution buffer (float2 stores)
#pragma unroll
    for (int mi = 0; mi < 2; mi++) {
        int r0 = wm * 32 + mi * 16 + gid;
        int   t0 = 0, t1 = 0, s0 = 0, s1 = 0;
        float gt0 = 0.f, gt1 = 0.f;
        bool v0 = r0 < mcnt, v1 = (r0 + 8) < mcnt;
        if (v0) { int p = m0 + r0;     t0 = g_pair_token[p]; gt0 = g_pair_gate[p]; s0 = g_pair_slot[p]; }
        if (v1) { int p = m0 + r0 + 8; t1 = g_pair_token[p]; gt1 = g_pair_gate[p]; s1 = g_pair_slot[p]; }
#pragma unroll
        for (int ni = 0; ni < 8; ni++) {
            int colg = nt * 128 + wn * 64 + ni * 8 + tig * 2;
            if (v0) {
                float2 v = make_float2(acc[mi][ni][0] * gt0, acc[mi][ni][1] * gt0);
                *(float2*)&g_contrib[s0][t0][colg] = v;
            }
            if (v1) {
                float2 v = make_float2(acc[mi][ni][2] * gt1, acc[mi][ni][3] * gt1);
                *(float2*)&g_contrib[s1][t1][colg] = v;
            }
        }
    }
}

// ---------------- kernel 4: final reduce -------------------------------------
__global__ void reduce_kernel(float* __restrict__ out) {
    size_t i = (size_t)blockIdx.x * blockDim.x + threadIdx.x;
    size_t n = (size_t)T_TOK * EMB / 4;
    if (i >= n) return;
    const float4* c0 = (const float4*)&g_contrib[0][0][0];
    const float4* c1 = (const float4*)&g_contrib[1][0][0];
    float4 a = c0[i], b = c1[i];
    ((float4*)out)[i] = make_float4(a.x + b.x, a.y + b.y, a.z + b.z, a.w + b.w);
}

// ---------------- launch ------------------------------------------------------
extern "C" void kernel_launch(void* const* d_in, const int* in_sizes, int n_in,
                              void* d_out, int out_size) {
    const float* x  = (const float*)d_in[0];
    const float* wr = (const float*)d_in[1];
    const float* w1 = (const float*)d_in[2];
    const float* w3 = (const float*)d_in[3];
    const float* w2 = (const float*)d_in[4];
    float* out = (float*)d_out;

    cudaFuncSetAttribute(ffn1_kernel, cudaFuncAttributeMaxDynamicSharedMemorySize, F1_SMEM);
    cudaFuncSetAttribute(ffn2_kernel, cudaFuncAttributeMaxDynamicSharedMemorySize, F2_SMEM);

    prep_kernel<<<dim3(88, 32, 25), 256>>>(w1, w3, w2, x, wr);         // 0 (preround + router)
    offsets_scatter_kernel<<<1, 256>>>();                              // 1

    ffn1_kernel<<<dim3(32, HID / 64, NE), 256, F1_SMEM>>>();           // 2
    ffn2_kernel<<<dim3(32, EMB / 128, NE), 256, F2_SMEM>>>();          // 3  <- ncu capture (new data!)
    reduce_kernel<<<((T_TOK * EMB / 4) + 255) / 256, 256>>>(out);      // 4
}